// round 5
// baseline (speedup 1.0000x reference)
#include <cuda_runtime.h>

#define Bd 8
#define Nd 65536
#define Cd 64
#define Md 64
#define CAP 36            // representative-mode slots (33 real + 3 pad)
#define Sp 64             // proj n-splits (blocks per batch)
#define TWOPI 6.283185307179586f

typedef unsigned long long ull;

// ---------------- device scratch (no allocation) ----------------
__device__ float g_rep_fx[CAP], g_rep_fy[CAP];
__device__ int   g_rep_m[CAP], g_rep_pair[CAP];
// per (split, b, warp) partial coeffs, packed (re, im): [Sp][Bd][8][36][64]
__device__ __align__(16) ull g_part[(size_t)Sp * Bd * 8 * CAP * Cd];
// combined recon coeffs, packed (A2, B2): [Bd][36][64]
__device__ __align__(16) ull g_W[Bd * CAP * Cd];

__device__ __forceinline__ ull pack2(float lo, float hi) {
    ull r; asm("mov.b64 %0, {%1, %2};" : "=l"(r) : "f"(lo), "f"(hi)); return r;
}
__device__ __forceinline__ float2 unpack2(ull v) {
    float lo, hi; asm("mov.b64 {%0, %1}, %2;" : "=f"(lo), "=f"(hi) : "l"(v));
    return make_float2(lo, hi);
}
__device__ __forceinline__ ull fma2(ull a, ull b, ull c) {
    ull d; asm("fma.rn.f32x2 %0, %1, %2, %3;" : "=l"(d) : "l"(a), "l"(b), "l"(c));
    return d;
}

// ---------------------------------------------------------------------------
// K0: discover conjugate pairs (serial thread-0; deterministic ordering).
// ---------------------------------------------------------------------------
__global__ void setup_kernel(const float* __restrict__ freqs) {
    if (threadIdx.x != 0 || blockIdx.x != 0) return;
    bool used[Md];
    for (int m = 0; m < Md; m++) used[m] = false;
    int cnt = 0;
    for (int m = 0; m < Md; m++) {
        if (used[m]) continue;
        float fx = freqs[2 * m], fy = freqs[2 * m + 1];
        int p = -1;
        for (int q = m + 1; q < Md; q++) {
            if (!used[q] && freqs[2 * q] == -fx && freqs[2 * q + 1] == -fy) { p = q; break; }
        }
        if (cnt < CAP) {
            g_rep_m[cnt] = m; g_rep_pair[cnt] = p;
            g_rep_fx[cnt] = fx; g_rep_fy[cnt] = fy;
            cnt++;
        }
        used[m] = true;
        if (p >= 0) used[p] = true;
    }
    for (int j = cnt; j < CAP; j++) {
        g_rep_m[j] = -1; g_rep_pair[j] = -1;
        g_rep_fx[j] = 0.0f; g_rep_fy[j] = 0.0f;
    }
}

// ---------------------------------------------------------------------------
// K1: projection.  Block = (split, b), 256 thr.  64-n tiles; 8 warps split n.
// Thread tile: 9 reps x 8 channels, acc packed (re, im).
// dyn smem: xdup[64][64] ull (x,x) | tcs[36][64] ull (cos,-sin) | sfx | sfy
// ---------------------------------------------------------------------------
#define PROJ_SMEM (64*64*8 + 36*64*8 + 36*4 + 36*4)
__global__ __launch_bounds__(256) void proj_kernel(
    const float* __restrict__ inputs,
    const float* __restrict__ coords)
{
    extern __shared__ __align__(16) char smem[];
    ull (*xdup)[Cd] = (ull(*)[Cd])smem;                      // 32 KB
    ull (*tcs)[64]  = (ull(*)[64])(smem + 64*64*8);          // 18 KB
    float* sfx = (float*)(smem + 64*64*8 + 36*64*8);
    float* sfy = sfx + CAP;

    const int tid  = threadIdx.x;
    const int warp = tid >> 5;
    const int lane = tid & 31;
    const int rg   = lane >> 3;          // rep group: reps rg*9 .. rg*9+8
    const int cg   = lane & 7;           // channel octet
    const int split = blockIdx.x;
    const int b     = blockIdx.y;

    if (tid < CAP) { sfx[tid] = g_rep_fx[tid]; sfy[tid] = g_rep_fy[tid]; }

    ull acc[9][8];
    #pragma unroll
    for (int q = 0; q < 9; q++)
        #pragma unroll
        for (int c = 0; c < 8; c++) acc[q][c] = 0;

    const int nbase = split * (Nd / Sp);                 // 1024 n per block
    const float2* cin = ((const float2*)coords) + (size_t)b * Nd;

    for (int tile = 0; tile < (Nd / Sp) / 64; tile++) {
        const int n0 = nbase + tile * 64;
        __syncthreads();   // previous main-loop reads done (also covers sfx init)

        // ---- fill x tile (duplicated-packed) ----
        const float4* xin4 = (const float4*)(inputs + ((size_t)b * Nd + n0) * Cd);
        #pragma unroll
        for (int k = 0; k < 4; k++) {
            const int idx = tid + 256 * k;               // 0..1023
            const float4 v = xin4[idx];
            const int nl = idx >> 4;
            const int c4 = (idx & 15) << 2;
            ulonglong2 p;
            p.x = pack2(v.x, v.x); p.y = pack2(v.y, v.y);
            *(ulonglong2*)&xdup[nl][c4] = p;
            p.x = pack2(v.z, v.z); p.y = pack2(v.w, v.w);
            *(ulonglong2*)&xdup[nl][c4 + 2] = p;
        }
        // ---- fill trig table (cos, -sin): 2304 entries, 9 per thread ----
        #pragma unroll
        for (int k = 0; k < 9; k++) {
            const int e = tid + 256 * k;
            const int r = e >> 6;
            const int nl = e & 63;
            const float2 cc = cin[n0 + nl];
            float t  = cc.x * sfx[r] + cc.y * sfy[r];    // integer freqs
            float ph = TWOPI * (t - rintf(t));
            float s, c;
            __sincosf(ph, &s, &c);
            tcs[r][nl] = pack2(c, -s);
        }
        __syncthreads();

        // ---- main: my warp handles n = warp*8 .. +7 ----
        for (int nn = 0; nn < 8; nn++) {
            const int nl = warp * 8 + nn;
            ull tf[9];
            #pragma unroll
            for (int q = 0; q < 9; q++) tf[q] = tcs[rg * 9 + q][nl];
            ull xv[8];
            {
                const ulonglong2* xr = (const ulonglong2*)&xdup[nl][cg * 8];
                ulonglong2 a = xr[0], bb = xr[1], c2 = xr[2], d = xr[3];
                xv[0] = a.x;  xv[1] = a.y;  xv[2] = bb.x; xv[3] = bb.y;
                xv[4] = c2.x; xv[5] = c2.y; xv[6] = d.x;  xv[7] = d.y;
            }
            #pragma unroll
            for (int q = 0; q < 9; q++)
                #pragma unroll
                for (int c = 0; c < 8; c++)
                    acc[q][c] = fma2(tf[q], xv[c], acc[q][c]);
        }
    }

    // ---- write per-warp partials ----
    ull* dst = g_part + ((((size_t)split * Bd + b) * 8 + warp) * CAP) * Cd;
    #pragma unroll
    for (int q = 0; q < 9; q++) {
        const int r = rg * 9 + q;
        #pragma unroll
        for (int c2 = 0; c2 < 4; c2++) {
            ulonglong2 v; v.x = acc[q][2 * c2]; v.y = acc[q][2 * c2 + 1];
            *(ulonglong2*)&dst[r * Cd + cg * 8 + 2 * c2] = v;
        }
    }
}

// ---------------------------------------------------------------------------
// K2: reduce 512 partials, apply 1/N + weight, fold conjugate pair; pack.
// ---------------------------------------------------------------------------
__global__ __launch_bounds__(256) void mix_kernel(
    const float* __restrict__ wre,
    const float* __restrict__ wim)
{
    const int idx = blockIdx.x * 256 + threadIdx.x;      // over Bd*CAP*Cd
    const int b  = idx / (CAP * Cd);
    const int jc = idx - b * (CAP * Cd);
    const int j  = jc >> 6;
    const int c  = jc & 63;

    float A2 = 0.0f, B2 = 0.0f;
    const int m = g_rep_m[j];
    if (m >= 0) {
        float cr = 0.0f, ci = 0.0f;
        const ull* p = g_part + ((size_t)b * 8) * (CAP * Cd) + j * Cd + c;
        for (int s = 0; s < Sp; s++) {
            #pragma unroll
            for (int w = 0; w < 8; w++) {
                const float2 v = unpack2(p[(size_t)w * (CAP * Cd)]);
                cr += v.x; ci += v.y;
            }
            p += (size_t)Bd * 8 * (CAP * Cd);
        }
        const float inv = 1.0f / (float)Nd;
        const float wr = wre[m * Cd + c], wi = wim[m * Cd + c];
        A2 =  (cr * wr - ci * wi) * inv;
        B2 = -(cr * wi + ci * wr) * inv;
        const int pp = g_rep_pair[j];
        if (pp >= 0) {
            const float wrp = wre[pp * Cd + c], wip = wim[pp * Cd + c];
            A2 += ( cr * wrp + ci * wip) * inv;
            B2 -= (-cr * wip + ci * wrp) * inv;
        }
    }
    g_W[idx] = pack2(A2, B2);
}

// ---------------------------------------------------------------------------
// K3: reconstruction.  Block = 256 n x 64 c; thread tile 8 n x 8 c.
// acc lanes: (sum cos*A2, sum sin*B2); out = lo + hi.
// dyn smem: tcs[36][256] ull (cos, sin) | sW[36][64] ull (A2, B2) | sfx | sfy
// ---------------------------------------------------------------------------
#define RECON_SMEM (36*256*8 + 36*64*8 + 36*4 + 36*4)
__global__ __launch_bounds__(256) void recon_kernel(
    const float* __restrict__ coords,
    float* __restrict__ out)
{
    extern __shared__ __align__(16) char smem[];
    ull (*tcs)[256] = (ull(*)[256])smem;                   // 72 KB
    ull (*sW)[Cd]   = (ull(*)[Cd])(smem + 36*256*8);       // 18 KB
    float* sfx = (float*)(smem + 36*256*8 + 36*64*8);
    float* sfy = sfx + CAP;

    const int tid = threadIdx.x;
    const int ng  = tid >> 3;      // n octet 0..31
    const int cg  = tid & 7;       // c octet
    const int b   = blockIdx.y;
    const int n0  = blockIdx.x * 256;

    // load W (packed) + freqs
    {
        const ulonglong2* src = (const ulonglong2*)(g_W + (size_t)b * CAP * Cd);
        ulonglong2* dw = (ulonglong2*)&sW[0][0];
        for (int i = tid; i < (CAP * Cd) / 2; i += 256) dw[i] = src[i];
    }
    if (tid < CAP) { sfx[tid] = g_rep_fx[tid]; sfy[tid] = g_rep_fy[tid]; }
    __syncthreads();

    // trig table: this thread owns n = tid, all 36 modes
    {
        const float2 cc = ((const float2*)coords)[(size_t)b * Nd + n0 + tid];
        for (int j = 0; j < CAP; j++) {
            float t  = cc.x * sfx[j] + cc.y * sfy[j];
            float ph = TWOPI * (t - rintf(t));
            float s, c;
            __sincosf(ph, &s, &c);
            tcs[j][tid] = pack2(c, s);
        }
    }
    __syncthreads();

    ull acc[8][8];
    #pragma unroll
    for (int i = 0; i < 8; i++)
        #pragma unroll
        for (int c = 0; c < 8; c++) acc[i][c] = 0;

    for (int j = 0; j < CAP; j++) {
        ull tf[8], wf[8];
        {
            const ulonglong2* tr = (const ulonglong2*)&tcs[j][ng * 8];
            ulonglong2 a = tr[0], bb = tr[1], c2 = tr[2], d = tr[3];
            tf[0] = a.x;  tf[1] = a.y;  tf[2] = bb.x; tf[3] = bb.y;
            tf[4] = c2.x; tf[5] = c2.y; tf[6] = d.x;  tf[7] = d.y;
        }
        {
            const ulonglong2* wr = (const ulonglong2*)&sW[j][cg * 8];
            ulonglong2 a = wr[0], bb = wr[1], c2 = wr[2], d = wr[3];
            wf[0] = a.x;  wf[1] = a.y;  wf[2] = bb.x; wf[3] = bb.y;
            wf[4] = c2.x; wf[5] = c2.y; wf[6] = d.x;  wf[7] = d.y;
        }
        #pragma unroll
        for (int nn = 0; nn < 8; nn++)
            #pragma unroll
            for (int c = 0; c < 8; c++)
                acc[nn][c] = fma2(tf[nn], wf[c], acc[nn][c]);
    }

    // writeout: out[n][c] = lo + hi
    #pragma unroll
    for (int nn = 0; nn < 8; nn++) {
        float4 o0, o1;
        float2 t;
        t = unpack2(acc[nn][0]); o0.x = t.x + t.y;
        t = unpack2(acc[nn][1]); o0.y = t.x + t.y;
        t = unpack2(acc[nn][2]); o0.z = t.x + t.y;
        t = unpack2(acc[nn][3]); o0.w = t.x + t.y;
        t = unpack2(acc[nn][4]); o1.x = t.x + t.y;
        t = unpack2(acc[nn][5]); o1.y = t.x + t.y;
        t = unpack2(acc[nn][6]); o1.z = t.x + t.y;
        t = unpack2(acc[nn][7]); o1.w = t.x + t.y;
        const size_t off = ((size_t)b * Nd + n0 + ng * 8 + nn) * Cd + cg * 8;
        *(float4*)(out + off)     = o0;
        *(float4*)(out + off + 4) = o1;
    }
}

// ---------------------------------------------------------------------------
extern "C" void kernel_launch(void* const* d_in, const int* in_sizes, int n_in,
                              void* d_out, int out_size)
{
    const float* inputs = (const float*)d_in[0];
    const float* coords = (const float*)d_in[1];
    const float* wre    = (const float*)d_in[2];
    const float* wim    = (const float*)d_in[3];
    const float* freqs  = (const float*)d_in[4];
    float* out = (float*)d_out;

    cudaFuncSetAttribute(proj_kernel,
        cudaFuncAttributeMaxDynamicSharedMemorySize, PROJ_SMEM);
    cudaFuncSetAttribute(recon_kernel,
        cudaFuncAttributeMaxDynamicSharedMemorySize, RECON_SMEM);

    setup_kernel<<<1, 32>>>(freqs);
    proj_kernel<<<dim3(Sp, Bd), 256, PROJ_SMEM>>>(inputs, coords);
    mix_kernel<<<(Bd * CAP * Cd) / 256, 256>>>(wre, wim);
    recon_kernel<<<dim3(Nd / 256, Bd), 256, RECON_SMEM>>>(coords, out);
}

// round 7
// speedup vs baseline: 2.5483x; 2.5483x over previous
#include <cuda_runtime.h>
#include <cuda_bf16.h>
#include <cstdint>

#define Bd 8
#define Nd 65536
#define Cd 64
#define Md 64
#define CAP 36
#define Sp 64
#define TWOPI 6.283185307179586f

typedef unsigned short ush;

// ---------------- device scratch (no allocation; statically zeroed) --------
__device__ float g_rep_fx[CAP], g_rep_fy[CAP];
__device__ int   g_rep_m[CAP], g_rep_pair[CAP];
__device__ float g_partial[(size_t)Sp * Bd * Cd * 80];   // [split][b][c][j2(80)]
__device__ ush   g_W[(size_t)Bd * Cd * 160];             // [b][c][160]; pads stay 0

// ---------------- helpers ----------------
__device__ __forceinline__ void splitb(float x, ush& h, ush& l) {
    uint32_t u = __float_as_uint(x);
    h = (ush)(u >> 16);                                   // truncation (exact hi)
    __nv_bfloat16 lb = __float2bfloat16(x - __uint_as_float(u & 0xFFFF0000u));
    l = *reinterpret_cast<ush*>(&lb);
}
__device__ __forceinline__ void trig_of(float2 cc, float fx, float fy,
                                        float& s, float& c) {
    float t = cc.x * fx + cc.y * fy;                      // integer freqs
    float ph = TWOPI * (t - rintf(t));                    // exact reduce to [-pi,pi]
    __sincosf(ph, &s, &c);
}
__device__ __forceinline__ uint32_t pk(ush a, ush b) {
    return (uint32_t)a | ((uint32_t)b << 16);
}
// D(16x8,f32) += A(16x16 row,bf16) * B(16x8 col,bf16)
__device__ __forceinline__ void hmma(float* d, const uint32_t* a, const uint32_t* b) {
    asm volatile(
        "mma.sync.aligned.m16n8k16.row.col.f32.bf16.bf16.f32 "
        "{%0,%1,%2,%3},{%4,%5,%6,%7},{%8,%9},{%0,%1,%2,%3};"
        : "+f"(d[0]), "+f"(d[1]), "+f"(d[2]), "+f"(d[3])
        : "r"(a[0]), "r"(a[1]), "r"(a[2]), "r"(a[3]), "r"(b[0]), "r"(b[1]));
}

// ---------------------------------------------------------------------------
// K0: conjugate-pair discovery (serial, deterministic)
// ---------------------------------------------------------------------------
__global__ void setup_kernel(const float* __restrict__ freqs) {
    if (threadIdx.x != 0 || blockIdx.x != 0) return;
    bool used[Md]; int cnt = 0;
    for (int m = 0; m < Md; m++) used[m] = false;
    for (int m = 0; m < Md; m++) {
        if (used[m]) continue;
        float fx = freqs[2 * m], fy = freqs[2 * m + 1];
        int p = -1;
        for (int q = m + 1; q < Md; q++)
            if (!used[q] && freqs[2 * q] == -fx && freqs[2 * q + 1] == -fy) { p = q; break; }
        if (cnt < CAP) {
            g_rep_m[cnt] = m; g_rep_pair[cnt] = p;
            g_rep_fx[cnt] = fx; g_rep_fy[cnt] = fy; cnt++;
        }
        used[m] = true; if (p >= 0) used[p] = true;
    }
    for (int j = cnt; j < CAP; j++) {
        g_rep_m[j] = -1; g_rep_pair[j] = -1; g_rep_fx[j] = 0.f; g_rep_fy[j] = 0.f;
    }
}

// ---------------------------------------------------------------------------
// K1 proj: D[c(64)][j2(80)] += X[c][k] * T[j2][k]  over n, bf16 hi/lo.
// smem: Xs[64][136]h | Ts[80][136]h | xs[64][68]f | sco[64]f2
// k regions (halves): hi 0..63, lo 64..127.
// ---------------------------------------------------------------------------
#define PSTR 136
#define PSTRW 68
#define XS_OFF 0
#define TS_OFF (64 * PSTR)                        // in halves
#define XSF_OFF (144 * PSTR * 2)                  // bytes: 39168 (16-aligned)
#define SCO_OFF (XSF_OFF + 64 * 68 * 4)           // 39168 + 17408 = 56576
#define PROJ_SMEM (SCO_OFF + 64 * 8)

__global__ __launch_bounds__(256) void proj_kernel(
    const float* __restrict__ inputs, const float* __restrict__ coords)
{
    extern __shared__ __align__(16) ush sm[];
    ush* Xs = sm + XS_OFF;
    ush* Ts = sm + TS_OFF;
    uint32_t* Xw = (uint32_t*)Xs;
    uint32_t* Tw = (uint32_t*)Ts;
    float (*xs)[68] = (float(*)[68])((char*)sm + XSF_OFF);
    float2* sco = (float2*)((char*)sm + SCO_OFF);

    const int tid = threadIdx.x, wid = tid >> 5, lane = tid & 31;
    const int g = lane >> 2, tq = lane & 3;
    const int split = blockIdx.x, b = blockIdx.y;

    // zero T tile once (rows 72-79 must stay zero)
    for (int i = tid; i < 80 * PSTRW; i += 256) Tw[i] = 0;

    const int mt = wid >> 1;                 // c tile: c0 = mt*16
    const int nb = (wid & 1) * 5;            // j2 tiles nb..nb+4

    float acc[5][4];
    #pragma unroll
    for (int u = 0; u < 5; u++)
        #pragma unroll
        for (int v = 0; v < 4; v++) acc[u][v] = 0.f;

    const int nbase = split * (Nd / Sp);
    const float2* cin = ((const float2*)coords) + (size_t)b * Nd;

    for (int t = 0; t < 16; t++) {
        const int n0 = nbase + t * 64;
        __syncthreads();                     // tiles & xs free
        // stage x [64n][64c] -> xs
        const float4* xin4 = (const float4*)(inputs + ((size_t)b * Nd + n0) * Cd);
        #pragma unroll
        for (int r = 0; r < 4; r++) {
            const int idx = tid + 256 * r;
            const float4 v = xin4[idx];
            *(float4*)&xs[idx >> 4][(idx & 15) << 2] = v;
        }
        if (tid < 64) sco[tid] = cin[n0 + tid];
        __syncthreads();

        // build X tile: c = tid>>2, n = 2q + 8i (conflict-free column reads)
        {
            const int c = tid >> 2, q = tid & 3;
            #pragma unroll
            for (int i = 0; i < 8; i++) {
                const int n = 2 * q + 8 * i;
                ush h0, l0, h1, l1;
                splitb(xs[n][c], h0, l0);
                splitb(xs[n + 1][c], h1, l1);
                Xw[c * PSTRW + (n >> 1)]      = pk(h0, h1);
                Xw[c * PSTRW + 32 + (n >> 1)] = pk(l0, l1);
            }
        }
        // build T tile: 1152 (j, n-pair) items
        for (int e = tid; e < 1152; e += 256) {
            const int j = e >> 5, n = (e & 31) * 2;
            const float fx = g_rep_fx[j], fy = g_rep_fy[j];
            float s0, c0, s1, c1;
            trig_of(sco[n], fx, fy, s0, c0);
            trig_of(sco[n + 1], fx, fy, s1, c1);
            ush ch0, cl0, sh0, sl0, ch1, cl1, sh1, sl1;
            splitb(c0, ch0, cl0); splitb(s0, sh0, sl0);
            splitb(c1, ch1, cl1); splitb(s1, sh1, sl1);
            Tw[j * PSTRW + (n >> 1)]             = pk(ch0, ch1);
            Tw[j * PSTRW + 32 + (n >> 1)]        = pk(cl0, cl1);
            Tw[(36 + j) * PSTRW + (n >> 1)]      = pk(sh0, sh1);
            Tw[(36 + j) * PSTRW + 32 + (n >> 1)] = pk(sl0, sl1);
        }
        __syncthreads();

        // MMA: 12 ksteps = 3 product groups x 4
        #pragma unroll
        for (int gr = 0; gr < 3; gr++) {
            const int kwAb = (gr == 1) ? 32 : 0;     // X lo for group 1
            const int kwBb = (gr == 2) ? 32 : 0;     // T lo for group 2
            #pragma unroll
            for (int s = 0; s < 4; s++) {
                const int kwA = kwAb + 8 * s, kwB = kwBb + 8 * s;
                uint32_t a[4];
                const int ra = (mt * 16 + g) * PSTRW + kwA + tq;
                a[0] = Xw[ra];              a[1] = Xw[ra + 8 * PSTRW];
                a[2] = Xw[ra + 4];          a[3] = Xw[ra + 8 * PSTRW + 4];
                #pragma unroll
                for (int u = 0; u < 5; u++) {
                    uint32_t bb[2];
                    const int rb = ((nb + u) * 8 + g) * PSTRW + kwB + tq;
                    bb[0] = Tw[rb]; bb[1] = Tw[rb + 4];
                    hmma(acc[u], a, bb);
                }
            }
        }
    }

    // epilogue: D[c][j2] -> g_partial[split][b][c][80]
    float* dst = g_partial + (((size_t)split * Bd + b) * Cd) * 80;
    #pragma unroll
    for (int u = 0; u < 5; u++) {
        const int j = (nb + u) * 8 + 2 * tq;
        const int c0 = mt * 16 + g;
        *(float2*)&dst[(size_t)c0 * 80 + j]       = make_float2(acc[u][0], acc[u][1]);
        *(float2*)&dst[(size_t)(c0 + 8) * 80 + j] = make_float2(acc[u][2], acc[u][3]);
    }
}

// ---------------------------------------------------------------------------
// K2 mix: reduce splits, 1/N + weight + conj fold, emit bf16 hi/lo W
// ---------------------------------------------------------------------------
__global__ __launch_bounds__(256) void mix_kernel(
    const float* __restrict__ wre, const float* __restrict__ wim)
{
    const int idx = blockIdx.x * 256 + threadIdx.x;       // Bd*36*64
    const int b = idx / (CAP * Cd), rem = idx - b * (CAP * Cd);
    const int j = rem >> 6, c = rem & 63;
    const int m = g_rep_m[j];
    if (m < 0) return;

    float cr = 0.f, si = 0.f;
    for (int s = 0; s < Sp; s++) {
        const float* p = g_partial + (((size_t)s * Bd + b) * Cd + c) * 80;
        cr += p[j];
        si += p[36 + j];
    }
    const float ci = -si, inv = 1.0f / (float)Nd;
    const float wr = wre[m * Cd + c], wi = wim[m * Cd + c];
    float A2 =  (cr * wr - ci * wi) * inv;                // cos-side coeff
    float B2 = -(cr * wi + ci * wr) * inv;                // sin-side coeff
    const int pp = g_rep_pair[j];
    if (pp >= 0) {
        const float wrp = wre[pp * Cd + c], wip = wim[pp * Cd + c];
        A2 += ( cr * wrp + ci * wip) * inv;
        B2 -= (-cr * wip + ci * wrp) * inv;
    }
    ush ah, al, bh, bl;
    splitb(A2, ah, al); splitb(B2, bh, bl);
    ush* W = g_W + ((size_t)b * Cd + c) * 160;
    W[j] = ah; W[36 + j] = bh; W[80 + j] = al; W[116 + j] = bl;
}

// ---------------------------------------------------------------------------
// K3 recon: D[n(128)][c(64)] = T[n][k] * W[c][k],  k regions hi 0..79, lo 80..159
// smem: Ts[128][168]h | Ws[64][168]h
// ---------------------------------------------------------------------------
#define RSTR 168
#define RSTRW 84
#define WS_OFF (128 * RSTR)                       // halves
#define RECON_SMEM ((128 + 64) * RSTR * 2)

__global__ __launch_bounds__(256) void recon_kernel(
    const float* __restrict__ coords, float* __restrict__ out)
{
    extern __shared__ __align__(16) ush sm[];
    ush* Ts = sm;
    ush* Ws = sm + WS_OFF;
    uint32_t* Twr = (uint32_t*)Ts;
    uint32_t* Wwr = (uint32_t*)Ws;

    const int tid = threadIdx.x, wid = tid >> 5, lane = tid & 31;
    const int g = lane >> 2, tq = lane & 3;
    const int b = blockIdx.y, n0 = blockIdx.x * 128;

    // zero both tiles (pad k-slots must be 0)
    for (int i = tid; i < (128 + 64) * RSTRW; i += 256) ((uint32_t*)sm)[i] = 0;
    __syncthreads();

    // W tile: [c][160 halves] = 20 uint4 per row
    for (int v = tid; v < 1280; v += 256) {
        const int c = v / 20, q = v - c * 20;
        const uint4 w = *(const uint4*)(g_W + ((size_t)b * Cd + c) * 160 + q * 8);
        *(uint4*)&Ws[c * RSTR + q * 8] = w;
    }
    // T tile: n = tid>>1, half h = tid&1 covers 18 modes
    {
        const int n = tid >> 1, h = tid & 1;
        const float2 cc = ((const float2*)coords)[(size_t)b * Nd + n0 + n];
        #pragma unroll
        for (int jj = 0; jj < 18; jj++) {
            const int j = 18 * h + jj;
            float s, c;
            trig_of(cc, g_rep_fx[j], g_rep_fy[j], s, c);
            ush ch, cl, sh, sl;
            splitb(c, ch, cl); splitb(s, sh, sl);
            Ts[n * RSTR + j]        = ch;
            Ts[n * RSTR + 36 + j]   = sh;
            Ts[n * RSTR + 80 + j]   = cl;
            Ts[n * RSTR + 116 + j]  = sl;
        }
    }
    __syncthreads();

    float acc[8][4];
    #pragma unroll
    for (int u = 0; u < 8; u++)
        #pragma unroll
        for (int v = 0; v < 4; v++) acc[u][v] = 0.f;

    // 15 ksteps = 3 groups x 5
    #pragma unroll
    for (int gr = 0; gr < 3; gr++) {
        const int kwAb = (gr == 1) ? 40 : 0;     // T lo for group 1
        const int kwBb = (gr == 2) ? 40 : 0;     // W lo for group 2
        #pragma unroll
        for (int s = 0; s < 5; s++) {
            const int kwA = kwAb + 8 * s, kwB = kwBb + 8 * s;
            uint32_t a[4];
            const int ra = (wid * 16 + g) * RSTRW + kwA + tq;
            a[0] = Twr[ra];             a[1] = Twr[ra + 8 * RSTRW];
            a[2] = Twr[ra + 4];         a[3] = Twr[ra + 8 * RSTRW + 4];
            #pragma unroll
            for (int u = 0; u < 8; u++) {
                uint32_t bb[2];
                const int rb = (u * 8 + g) * RSTRW + kwB + tq;
                bb[0] = Wwr[rb]; bb[1] = Wwr[rb + 4];
                hmma(acc[u], a, bb);
            }
        }
    }

    // epilogue: D[n][c] -> out
    const int r0 = wid * 16 + g;
    float* o0 = out + ((size_t)b * Nd + n0 + r0) * Cd;
    float* o1 = o0 + 8 * Cd;
    #pragma unroll
    for (int u = 0; u < 8; u++) {
        const int c = u * 8 + 2 * tq;
        *(float2*)&o0[c] = make_float2(acc[u][0], acc[u][1]);
        *(float2*)&o1[c] = make_float2(acc[u][2], acc[u][3]);
    }
}

// ---------------------------------------------------------------------------
extern "C" void kernel_launch(void* const* d_in, const int* in_sizes, int n_in,
                              void* d_out, int out_size)
{
    const float* inputs = (const float*)d_in[0];
    const float* coords = (const float*)d_in[1];
    const float* wre    = (const float*)d_in[2];
    const float* wim    = (const float*)d_in[3];
    const float* freqs  = (const float*)d_in[4];
    float* out = (float*)d_out;

    cudaFuncSetAttribute(proj_kernel,  cudaFuncAttributeMaxDynamicSharedMemorySize, PROJ_SMEM);
    cudaFuncSetAttribute(recon_kernel, cudaFuncAttributeMaxDynamicSharedMemorySize, RECON_SMEM);

    setup_kernel<<<1, 32>>>(freqs);
    proj_kernel<<<dim3(Sp, Bd), 256, PROJ_SMEM>>>(inputs, coords);
    mix_kernel<<<(Bd * CAP * Cd) / 256, 256>>>(wre, wim);
    recon_kernel<<<dim3(Nd / 128, Bd), 256, RECON_SMEM>>>(coords, out);
}